// round 4
// baseline (speedup 1.0000x reference)
#include <cuda_runtime.h>

#define HW 50176
#define W_ 224
#define H_ 224
#define SEGS 8
#define SEG_ROWS 28          // 224 / 8
#define QPR 56               // quads per row (224/4)
#define RG8 28               // 8-row groups per plane (224/8)

__device__ float g_part[1024 * SEGS];   // per-(image,segment) partial sums
__device__ float g_gm[1024];            // per-image gray mean

// ---------------------------------------------------------------------------
// Kernel 1: balanced partial reduction. Accumulation ORDER frozen (bitwise)
// from R2/R3 — gm's fp value determines solarize-threshold flips.
// Only change: interior quads hoist coef (identical expression => identical
// float => identical acc sequence).
// ---------------------------------------------------------------------------
__global__ void __launch_bounds__(256)
reduce_kernel(const float* __restrict__ x,
              const float* __restrict__ stdv) {
    const int b = blockIdx.x >> 3;
    const int s = blockIdx.x & 7;
    const float* p = x + (size_t)b * 3 * HW + s * SEG_ROWS * W_;

    const float gw0 = 0.299f * stdv[0];
    const float gw1 = 0.587f * stdv[1];
    const float gw2 = 0.114f * stdv[2];

    float acc = 0.f;
    for (int i = threadIdx.x; i < SEG_ROWS * W_ / 4; i += 256) {
        const int pix = i * 4;
        const int lr = pix / W_;
        const int c0 = pix - lr * W_;
        const int gr = s * SEG_ROWS + lr;
        float4 a0 = *(const float4*)(p + pix);
        float4 a1 = *(const float4*)(p + HW + pix);
        float4 a2 = *(const float4*)(p + 2 * HW + pix);
        const float ny = (gr == 0 || gr == H_ - 1) ? 2.f : 3.f;

        float e0[4] = {a0.x, a0.y, a0.z, a0.w};
        float e1[4] = {a1.x, a1.y, a1.z, a1.w};
        float e2[4] = {a2.x, a2.y, a2.z, a2.w};

        if (c0 != 0 && c0 != W_ - 4) {
            // interior quad: nx = 3 for all 4 lanes; same expression as per-j
            const float coef = 0.64f + 0.36f * (ny * 3.f + 4.f) * (1.f / 13.f);
#pragma unroll
            for (int j = 0; j < 4; j++) {
                const float gx = gw0 * e0[j] + gw1 * e1[j] + gw2 * e2[j];
                acc += coef * gx;
            }
        } else {
#pragma unroll
            for (int j = 0; j < 4; j++) {
                const int c = c0 + j;
                const float nx = (c == 0 || c == W_ - 1) ? 2.f : 3.f;
                const float coef = 0.64f + 0.36f * (ny * nx + 4.f) * (1.f / 13.f);
                const float gx = gw0 * e0[j] + gw1 * e1[j] + gw2 * e2[j];
                acc += coef * gx;
            }
        }
    }

    __shared__ float red[8];
#pragma unroll
    for (int off = 16; off > 0; off >>= 1)
        acc += __shfl_down_sync(0xffffffffu, acc, off);
    const int lane = threadIdx.x & 31;
    const int warp = threadIdx.x >> 5;
    if (lane == 0) red[warp] = acc;
    __syncthreads();
    if (threadIdx.x == 0) {
        float t = 0.f;
#pragma unroll
        for (int w = 0; w < 8; w++) t += red[w];
        g_part[blockIdx.x] = t;
    }
}

// ---------------------------------------------------------------------------
// Kernel 1b: finalize gm per image (bitwise same formula as R3's inline calc).
// ---------------------------------------------------------------------------
__global__ void gm_finalize(const float* __restrict__ mean, int B) {
    const int b = blockIdx.x * 256 + threadIdx.x;
    if (b >= B) return;
    float ps = 0.f;
#pragma unroll
    for (int i = 0; i < SEGS; i++) ps += g_part[b * SEGS + i];
    const double SC = 0.64 * (double)HW + 0.36 * (448900.0 + 4.0 * HW) / 13.0;
    const float cm = 0.299f * mean[0] + 0.587f * mean[1] + 0.114f * mean[2];
    g_gm[b] = (ps + cm * (float)SC) * (1.0f / (float)HW);
}

// ---------------------------------------------------------------------------
// Kernel 2: rolling-window fused pipeline. Thread = one column-quad x 8
// output rows. 10 LDG.128, halos via shuffle, collapsed linear algebra:
//   y2 = C1*cen + C2*total9 + G,  z = solarize,  out = (z-m)*inv_sd
// ---------------------------------------------------------------------------
struct RowRegs { float4 v; float L, R; };

__device__ __forceinline__ RowRegs load_row(const float* __restrict__ p,
                                            int row, int q, unsigned lane,
                                            float sd, float m) {
    RowRegs rr;
    const bool ok = (row >= 0 && row < H_);
    if (ok) {
        float4 u = *(const float4*)(p + row * W_);
        rr.v.x = fmaf(u.x, sd, m);
        rr.v.y = fmaf(u.y, sd, m);
        rr.v.z = fmaf(u.z, sd, m);
        rr.v.w = fmaf(u.w, sd, m);
    } else {
        rr.v = make_float4(0.f, 0.f, 0.f, 0.f);
    }
    rr.L = __shfl_up_sync(0xffffffffu, rr.v.w, 1);
    rr.R = __shfl_down_sync(0xffffffffu, rr.v.x, 1);
    if (q == 0)                 rr.L = 0.f;
    else if (lane == 0)         rr.L = ok ? fmaf(p[row * W_ - 1], sd, m) : 0.f;
    if (q == QPR - 1)           rr.R = 0.f;
    else if (lane == 31)        rr.R = ok ? fmaf(p[row * W_ + 4], sd, m) : 0.f;
    return rr;
}

__global__ void __launch_bounds__(256)
main_kernel(const float* __restrict__ x,
            const float* __restrict__ mean,
            const float* __restrict__ stdv,
            float* __restrict__ out,
            int nplanes) {
    const int idx = blockIdx.x * 256 + threadIdx.x;
    const int q = idx % QPR;
    const int t2 = idx / QPR;
    const int rg = t2 % RG8;
    const int plane = t2 / RG8;
    if (plane >= nplanes) return;

    const int b = plane / 3;
    const int ch = plane - b * 3;
    const float m = mean[ch];
    const float sd = stdv[ch];
    const float inv_sd = 1.0f / sd;     // divide AFTER solarize: <=1ulp effect
    const float gm = g_gm[b];

    // collapsed constants (double -> float once)
    const float C1 = (float)(0.4096 * (0.64 + 1.44 / 13.0));  // cen coeff
    const float C2 = (float)(0.4096 * 0.36 / 13.0);           // total9 coeff
    const float G  = (float)(0.64 * 0.36) * gm;               // gm term

    const unsigned lane = threadIdx.x & 31;
    const int c4 = q * 4;
    const int r0 = rg * 8;
    const float* p = x + (size_t)plane * HW + c4;
    float* ob = out + (size_t)plane * HW + r0 * W_ + c4;

    RowRegs w[3];
    w[0] = load_row(p, r0 - 1, q, lane, sd, m);
    w[1] = load_row(p, r0,     q, lane, sd, m);

#pragma unroll
    for (int o = 0; o < 8; o++) {
        w[(o + 2) % 3] = load_row(p, r0 + 1 + o, q, lane, sd, m);

        const RowRegs& t = w[o % 3];
        const RowRegs& mi = w[(o + 1) % 3];
        const RowRegs& bo = w[(o + 2) % 3];

        // column sums (shared across the 4 outputs of the quad)
        float cs0 = t.L   + mi.L   + bo.L;
        float cs1 = t.v.x + mi.v.x + bo.v.x;
        float cs2 = t.v.y + mi.v.y + bo.v.y;
        float cs3 = t.v.z + mi.v.z + bo.v.z;
        float cs4 = t.v.w + mi.v.w + bo.v.w;
        float cs5 = t.R   + mi.R   + bo.R;

        const float cen[4] = {mi.v.x, mi.v.y, mi.v.z, mi.v.w};
        const float tot[4] = {cs0 + cs1 + cs2, cs1 + cs2 + cs3,
                              cs2 + cs3 + cs4, cs3 + cs4 + cs5};

        float4 ov;
        float* op = (float*)&ov;
#pragma unroll
        for (int j = 0; j < 4; j++) {
            const float y2 = fmaf(cen[j], C1, fmaf(tot[j], C2, G));
            const float z = (y2 < 0.3f) ? y2 : 1.0f - y2;
            op[j] = (z - m) * inv_sd;
        }
        *(float4*)(ob + o * W_) = ov;
    }
}

extern "C" void kernel_launch(void* const* d_in, const int* in_sizes, int n_in,
                              void* d_out, int out_size) {
    const float* x    = (const float*)d_in[0];
    const float* mean = (const float*)d_in[1];
    const float* stdv = (const float*)d_in[2];
    float* out = (float*)d_out;

    const int B = in_sizes[0] / (3 * HW);
    const int nplanes = B * 3;

    reduce_kernel<<<B * SEGS, 256>>>(x, stdv);
    gm_finalize<<<(B + 255) / 256, 256>>>(mean, B);

    const int total = nplanes * RG8 * QPR;
    main_kernel<<<(total + 255) / 256, 256>>>(x, mean, stdv, out, nplanes);
}

// round 5
// speedup vs baseline: 1.2685x; 1.2685x over previous
#include <cuda_runtime.h>

#define HW 50176
#define W_ 224
#define H_ 224
#define SEGS 8
#define SEG_ROWS 28          // 224 / 8
#define QPR 56               // quads per row (224/4)
#define RG  56               // 4-row groups per plane (224/4)

__device__ float g_part[1024 * SEGS];   // per-(image,segment) partial sums
__device__ float g_gm[1024];            // per-image gray mean

// ---------------------------------------------------------------------------
// Kernel 1: balanced partial reduction. Accumulation ORDER frozen (bitwise).
// At 27.4us / DRAM 71% this is near its roofline — unchanged from R4.
// ---------------------------------------------------------------------------
__global__ void __launch_bounds__(256)
reduce_kernel(const float* __restrict__ x,
              const float* __restrict__ stdv) {
    const int b = blockIdx.x >> 3;
    const int s = blockIdx.x & 7;
    const float* p = x + (size_t)b * 3 * HW + s * SEG_ROWS * W_;

    const float gw0 = 0.299f * stdv[0];
    const float gw1 = 0.587f * stdv[1];
    const float gw2 = 0.114f * stdv[2];

    float acc = 0.f;
    for (int i = threadIdx.x; i < SEG_ROWS * W_ / 4; i += 256) {
        const int pix = i * 4;
        const int lr = pix / W_;
        const int c0 = pix - lr * W_;
        const int gr = s * SEG_ROWS + lr;
        float4 a0 = *(const float4*)(p + pix);
        float4 a1 = *(const float4*)(p + HW + pix);
        float4 a2 = *(const float4*)(p + 2 * HW + pix);
        const float ny = (gr == 0 || gr == H_ - 1) ? 2.f : 3.f;

        float e0[4] = {a0.x, a0.y, a0.z, a0.w};
        float e1[4] = {a1.x, a1.y, a1.z, a1.w};
        float e2[4] = {a2.x, a2.y, a2.z, a2.w};

        if (c0 != 0 && c0 != W_ - 4) {
            const float coef = 0.64f + 0.36f * (ny * 3.f + 4.f) * (1.f / 13.f);
#pragma unroll
            for (int j = 0; j < 4; j++) {
                const float gx = gw0 * e0[j] + gw1 * e1[j] + gw2 * e2[j];
                acc += coef * gx;
            }
        } else {
#pragma unroll
            for (int j = 0; j < 4; j++) {
                const int c = c0 + j;
                const float nx = (c == 0 || c == W_ - 1) ? 2.f : 3.f;
                const float coef = 0.64f + 0.36f * (ny * nx + 4.f) * (1.f / 13.f);
                const float gx = gw0 * e0[j] + gw1 * e1[j] + gw2 * e2[j];
                acc += coef * gx;
            }
        }
    }

    __shared__ float red[8];
#pragma unroll
    for (int off = 16; off > 0; off >>= 1)
        acc += __shfl_down_sync(0xffffffffu, acc, off);
    const int lane = threadIdx.x & 31;
    const int warp = threadIdx.x >> 5;
    if (lane == 0) red[warp] = acc;
    __syncthreads();
    if (threadIdx.x == 0) {
        float t = 0.f;
#pragma unroll
        for (int w = 0; w < 8; w++) t += red[w];
        g_part[blockIdx.x] = t;
    }
}

// ---------------------------------------------------------------------------
// Kernel 1b: finalize gm per image (bitwise-identical formula).
// ---------------------------------------------------------------------------
__global__ void gm_finalize(const float* __restrict__ mean, int B) {
    const int b = blockIdx.x * 256 + threadIdx.x;
    if (b >= B) return;
    float ps = 0.f;
#pragma unroll
    for (int i = 0; i < SEGS; i++) ps += g_part[b * SEGS + i];
    const double SC = 0.64 * (double)HW + 0.36 * (448900.0 + 4.0 * HW) / 13.0;
    const float cm = 0.299f * mean[0] + 0.587f * mean[1] + 0.114f * mean[2];
    g_gm[b] = (ps + cm * (float)SC) * (1.0f / (float)HW);
}

// ---------------------------------------------------------------------------
// Kernel 2: R3 structure (thread = quad x 4 rows, 6 front-batched LDG.128,
// halos via shuffle) + R4 algebra (y2 = C1*cen + C2*total9 + G, fma output).
// ---------------------------------------------------------------------------
__global__ void __launch_bounds__(256)
main_kernel(const float* __restrict__ x,
            const float* __restrict__ mean,
            const float* __restrict__ stdv,
            float* __restrict__ out,
            int nplanes) {
    const int idx = blockIdx.x * 256 + threadIdx.x;
    const int q = idx % QPR;                  // column quad 0..55
    const int t2 = idx / QPR;
    const int rg = t2 % RG;                   // row group 0..55
    const int plane = t2 / RG;
    if (plane >= nplanes) return;

    const int b = plane / 3;
    const int ch = plane - b * 3;
    const float m = mean[ch];
    const float sd = stdv[ch];
    const float inv_sd = 1.0f / sd;
    const float nmo = -m * inv_sd;            // out = fma(z, inv_sd, nmo)
    const float gm = g_gm[b];

    const float C1 = (float)(0.4096 * (0.64 + 1.44 / 13.0));  // center coeff
    const float C2 = (float)(0.4096 * 0.36 / 13.0);           // total9 coeff
    const float G  = (float)(0.64 * 0.36) * gm;               // gm term

    const float* p = x + (size_t)plane * HW;
    const int c4 = q * 4;
    const int r0 = rg * 4;

    // ---- 6 source rows (r0-1 .. r0+4), front-batched loads, affine ----
    float4 v[6];
#pragma unroll
    for (int k = 0; k < 6; k++) {
        const int row = r0 - 1 + k;
        if (row >= 0 && row < H_) {
            float4 u = *(const float4*)(p + row * W_ + c4);
            v[k].x = fmaf(u.x, sd, m);
            v[k].y = fmaf(u.y, sd, m);
            v[k].z = fmaf(u.z, sd, m);
            v[k].w = fmaf(u.w, sd, m);
        } else {
            v[k] = make_float4(0.f, 0.f, 0.f, 0.f);
        }
    }

    // ---- horizontal halos: shuffle interior, scalar LDG only at edges ----
    const unsigned lane = threadIdx.x & 31;
    float L[6], R[6];
#pragma unroll
    for (int k = 0; k < 6; k++) {
        L[k] = __shfl_up_sync(0xffffffffu, v[k].w, 1);
        R[k] = __shfl_down_sync(0xffffffffu, v[k].x, 1);
    }
    if (q == 0) {
#pragma unroll
        for (int k = 0; k < 6; k++) L[k] = 0.f;
    } else if (lane == 0) {
#pragma unroll
        for (int k = 0; k < 6; k++) {
            const int row = r0 - 1 + k;
            L[k] = (row >= 0 && row < H_) ? fmaf(p[row * W_ + c4 - 1], sd, m) : 0.f;
        }
    }
    if (q == QPR - 1) {
#pragma unroll
        for (int k = 0; k < 6; k++) R[k] = 0.f;
    } else if (lane == 31) {
#pragma unroll
        for (int k = 0; k < 6; k++) {
            const int row = r0 - 1 + k;
            R[k] = (row >= 0 && row < H_) ? fmaf(p[row * W_ + c4 + 4], sd, m) : 0.f;
        }
    }

    // ---- 4 output rows ----
    float* ob = out + (size_t)plane * HW + r0 * W_ + c4;

#pragma unroll
    for (int o = 0; o < 4; o++) {
        // column sums over the 3-row window (serve all 4 pixels of the quad)
        const float cs0 = L[o]   + L[o + 1]   + L[o + 2];
        const float cs1 = v[o].x + v[o + 1].x + v[o + 2].x;
        const float cs2 = v[o].y + v[o + 1].y + v[o + 2].y;
        const float cs3 = v[o].z + v[o + 1].z + v[o + 2].z;
        const float cs4 = v[o].w + v[o + 1].w + v[o + 2].w;
        const float cs5 = R[o]   + R[o + 1]   + R[o + 2];

        const float cen[4] = {v[o + 1].x, v[o + 1].y, v[o + 1].z, v[o + 1].w};
        const float tot[4] = {cs0 + cs1 + cs2, cs1 + cs2 + cs3,
                              cs2 + cs3 + cs4, cs3 + cs4 + cs5};

        float4 ov;
        float* op = (float*)&ov;
#pragma unroll
        for (int j = 0; j < 4; j++) {
            const float y2 = fmaf(cen[j], C1, fmaf(tot[j], C2, G));
            const float z = (y2 < 0.3f) ? y2 : 1.0f - y2;
            op[j] = fmaf(z, inv_sd, nmo);
        }
        *(float4*)(ob + o * W_) = ov;
    }
}

extern "C" void kernel_launch(void* const* d_in, const int* in_sizes, int n_in,
                              void* d_out, int out_size) {
    const float* x    = (const float*)d_in[0];
    const float* mean = (const float*)d_in[1];
    const float* stdv = (const float*)d_in[2];
    float* out = (float*)d_out;

    const int B = in_sizes[0] / (3 * HW);
    const int nplanes = B * 3;

    reduce_kernel<<<B * SEGS, 256>>>(x, stdv);
    gm_finalize<<<(B + 255) / 256, 256>>>(mean, B);

    const int total = nplanes * RG * QPR;
    main_kernel<<<(total + 255) / 256, 256>>>(x, mean, stdv, out, nplanes);
}

// round 6
// speedup vs baseline: 1.3528x; 1.0665x over previous
#include <cuda_runtime.h>

#define HW 50176
#define W_ 224
#define H_ 224
#define SEGS 8
#define SEG_ROWS 28          // 224 / 8
#define QPR 56               // quads per row (224/4)
#define RG  56               // 4-row groups per plane (224/4)

__device__ float g_part[1024 * SEGS];   // per-(image,segment) partial sums
__device__ float g_gm[1024];            // per-image gray mean
__device__ int   g_cnt[1024];           // arrival tickets (zero-init, self-resetting)

// ---------------------------------------------------------------------------
// Kernel 1: balanced partial reduction + fused gm finalize.
// Per-thread accumulation ORDER frozen (bitwise) — gm's fp value determines
// solarize-threshold flips. Software pipelining only reorders LOAD ISSUE,
// not the acc += sequence. Last block per image finalizes gm (same summation
// loop as the old gm_finalize => bitwise-identical gm) and resets the ticket.
// ---------------------------------------------------------------------------
__global__ void __launch_bounds__(256)
reduce_kernel(const float* __restrict__ x,
              const float* __restrict__ mean,
              const float* __restrict__ stdv) {
    const int b = blockIdx.x >> 3;
    const int s = blockIdx.x & 7;
    const float* p = x + (size_t)b * 3 * HW + s * SEG_ROWS * W_;

    const float gw0 = 0.299f * stdv[0];
    const float gw1 = 0.587f * stdv[1];
    const float gw2 = 0.114f * stdv[2];

    const int npix = SEG_ROWS * W_ / 4;   // 1568 quads
    float acc = 0.f;

    int i = threadIdx.x;
    // prologue load
    float4 a0 = *(const float4*)(p + i * 4);
    float4 a1 = *(const float4*)(p + HW + i * 4);
    float4 a2 = *(const float4*)(p + 2 * HW + i * 4);

    while (i < npix) {
        const int nx_i = i + 256;
        float4 b0, b1, b2;
        if (nx_i < npix) {                 // prefetch next iteration
            b0 = *(const float4*)(p + nx_i * 4);
            b1 = *(const float4*)(p + HW + nx_i * 4);
            b2 = *(const float4*)(p + 2 * HW + nx_i * 4);
        }

        const int pix = i * 4;
        const int lr = pix / W_;
        const int c0 = pix - lr * W_;
        const int gr = s * SEG_ROWS + lr;
        const float ny = (gr == 0 || gr == H_ - 1) ? 2.f : 3.f;

        float e0[4] = {a0.x, a0.y, a0.z, a0.w};
        float e1[4] = {a1.x, a1.y, a1.z, a1.w};
        float e2[4] = {a2.x, a2.y, a2.z, a2.w};

        if (c0 != 0 && c0 != W_ - 4) {
            const float coef = 0.64f + 0.36f * (ny * 3.f + 4.f) * (1.f / 13.f);
#pragma unroll
            for (int j = 0; j < 4; j++) {
                const float gx = gw0 * e0[j] + gw1 * e1[j] + gw2 * e2[j];
                acc += coef * gx;
            }
        } else {
#pragma unroll
            for (int j = 0; j < 4; j++) {
                const int c = c0 + j;
                const float nxw = (c == 0 || c == W_ - 1) ? 2.f : 3.f;
                const float coef = 0.64f + 0.36f * (ny * nxw + 4.f) * (1.f / 13.f);
                const float gx = gw0 * e0[j] + gw1 * e1[j] + gw2 * e2[j];
                acc += coef * gx;
            }
        }

        a0 = b0; a1 = b1; a2 = b2;
        i = nx_i;
    }

    __shared__ float red[8];
    __shared__ bool amLast;
#pragma unroll
    for (int off = 16; off > 0; off >>= 1)
        acc += __shfl_down_sync(0xffffffffu, acc, off);
    const int lane = threadIdx.x & 31;
    const int warp = threadIdx.x >> 5;
    if (lane == 0) red[warp] = acc;
    __syncthreads();
    if (threadIdx.x == 0) {
        float t = 0.f;
#pragma unroll
        for (int w = 0; w < 8; w++) t += red[w];
        g_part[blockIdx.x] = t;
        __threadfence();
        const int old = atomicAdd(&g_cnt[b], 1);
        amLast = (old == SEGS - 1);
    }
    __syncthreads();
    if (amLast && threadIdx.x == 0) {
        __threadfence();                   // acquire all 8 g_part writes
        float ps = 0.f;
#pragma unroll
        for (int k = 0; k < SEGS; k++) ps += g_part[b * SEGS + k];
        const double SC = 0.64 * (double)HW + 0.36 * (448900.0 + 4.0 * HW) / 13.0;
        const float cm = 0.299f * mean[0] + 0.587f * mean[1] + 0.114f * mean[2];
        g_gm[b] = (ps + cm * (float)SC) * (1.0f / (float)HW);
        g_cnt[b] = 0;                      // reset for next graph replay
    }
}

// ---------------------------------------------------------------------------
// Kernel 2: R5 structure/algebra, unchanged per-pixel math. Two changes:
//   * planes traversed in REVERSE so first reads hit the x-tail left in L2
//     by reduce_kernel (L2 126MB vs x 147MB),
//   * output written with __stwt (write-through) to avoid evicting x.
// ---------------------------------------------------------------------------
__global__ void __launch_bounds__(256)
main_kernel(const float* __restrict__ x,
            const float* __restrict__ mean,
            const float* __restrict__ stdv,
            float* __restrict__ out,
            int nplanes) {
    const int idx = blockIdx.x * 256 + threadIdx.x;
    const int q = idx % QPR;                  // column quad 0..55
    const int t2 = idx / QPR;
    const int rg = t2 % RG;                   // row group 0..55
    int plane = t2 / RG;
    if (plane >= nplanes) return;
    plane = nplanes - 1 - plane;              // reverse traversal for L2 reuse

    const int b = plane / 3;
    const int ch = plane - b * 3;
    const float m = mean[ch];
    const float sd = stdv[ch];
    const float inv_sd = 1.0f / sd;
    const float nmo = -m * inv_sd;
    const float gm = g_gm[b];

    const float C1 = (float)(0.4096 * (0.64 + 1.44 / 13.0));
    const float C2 = (float)(0.4096 * 0.36 / 13.0);
    const float G  = (float)(0.64 * 0.36) * gm;

    const float* p = x + (size_t)plane * HW;
    const int c4 = q * 4;
    const int r0 = rg * 4;

    // ---- 6 source rows (r0-1 .. r0+4), front-batched loads, affine ----
    float4 v[6];
#pragma unroll
    for (int k = 0; k < 6; k++) {
        const int row = r0 - 1 + k;
        if (row >= 0 && row < H_) {
            float4 u = *(const float4*)(p + row * W_ + c4);
            v[k].x = fmaf(u.x, sd, m);
            v[k].y = fmaf(u.y, sd, m);
            v[k].z = fmaf(u.z, sd, m);
            v[k].w = fmaf(u.w, sd, m);
        } else {
            v[k] = make_float4(0.f, 0.f, 0.f, 0.f);
        }
    }

    // ---- horizontal halos: shuffle interior, scalar LDG only at edges ----
    const unsigned lane = threadIdx.x & 31;
    float L[6], R[6];
#pragma unroll
    for (int k = 0; k < 6; k++) {
        L[k] = __shfl_up_sync(0xffffffffu, v[k].w, 1);
        R[k] = __shfl_down_sync(0xffffffffu, v[k].x, 1);
    }
    if (q == 0) {
#pragma unroll
        for (int k = 0; k < 6; k++) L[k] = 0.f;
    } else if (lane == 0) {
#pragma unroll
        for (int k = 0; k < 6; k++) {
            const int row = r0 - 1 + k;
            L[k] = (row >= 0 && row < H_) ? fmaf(p[row * W_ + c4 - 1], sd, m) : 0.f;
        }
    }
    if (q == QPR - 1) {
#pragma unroll
        for (int k = 0; k < 6; k++) R[k] = 0.f;
    } else if (lane == 31) {
#pragma unroll
        for (int k = 0; k < 6; k++) {
            const int row = r0 - 1 + k;
            R[k] = (row >= 0 && row < H_) ? fmaf(p[row * W_ + c4 + 4], sd, m) : 0.f;
        }
    }

    // ---- 4 output rows ----
    float* ob = out + (size_t)plane * HW + r0 * W_ + c4;

#pragma unroll
    for (int o = 0; o < 4; o++) {
        const float cs0 = L[o]   + L[o + 1]   + L[o + 2];
        const float cs1 = v[o].x + v[o + 1].x + v[o + 2].x;
        const float cs2 = v[o].y + v[o + 1].y + v[o + 2].y;
        const float cs3 = v[o].z + v[o + 1].z + v[o + 2].z;
        const float cs4 = v[o].w + v[o + 1].w + v[o + 2].w;
        const float cs5 = R[o]   + R[o + 1]   + R[o + 2];

        const float cen[4] = {v[o + 1].x, v[o + 1].y, v[o + 1].z, v[o + 1].w};
        const float tot[4] = {cs0 + cs1 + cs2, cs1 + cs2 + cs3,
                              cs2 + cs3 + cs4, cs3 + cs4 + cs5};

        float4 ov;
        float* op = (float*)&ov;
#pragma unroll
        for (int j = 0; j < 4; j++) {
            const float y2 = fmaf(cen[j], C1, fmaf(tot[j], C2, G));
            const float z = (y2 < 0.3f) ? y2 : 1.0f - y2;
            op[j] = fmaf(z, inv_sd, nmo);
        }
        __stwt((float4*)(ob + o * W_), ov);    // write-through, no L2 allocate
    }
}

extern "C" void kernel_launch(void* const* d_in, const int* in_sizes, int n_in,
                              void* d_out, int out_size) {
    const float* x    = (const float*)d_in[0];
    const float* mean = (const float*)d_in[1];
    const float* stdv = (const float*)d_in[2];
    float* out = (float*)d_out;

    const int B = in_sizes[0] / (3 * HW);
    const int nplanes = B * 3;

    reduce_kernel<<<B * SEGS, 256>>>(x, mean, stdv);

    const int total = nplanes * RG * QPR;
    main_kernel<<<(total + 255) / 256, 256>>>(x, mean, stdv, out, nplanes);
}